// round 1
// baseline (speedup 1.0000x reference)
#include <cuda_runtime.h>
#include <math.h>

#define NSPAT (64*64*64)
#define OFFSETS_OFF (2*5*NSPAT)
#define LOSS_OFF (2*5*NSPAT + 2*3*NSPAT)

__constant__ float c_cls_w[5*64*27];
__constant__ float c_cls_b[5];
__constant__ float c_off_w[3*64*27];
__constant__ float c_off_b[3];

__device__ int    g_best[128];   // best anchor per (b, gt)
__device__ double g_loss[1];

// ---------------------------------------------------------------------------
// Fused conv: 8 output channels (5 cls + 3 off), 3x3x3 SAME, direct, smem tiled
// ---------------------------------------------------------------------------
__global__ __launch_bounds__(512) void conv_kernel(const float* __restrict__ feat,
                                                   float* __restrict__ out) {
    int b     = blockIdx.z >> 3;
    int ztile = blockIdx.z & 7;
    int z0 = ztile * 8, y0 = blockIdx.y * 8, x0 = blockIdx.x * 8;
    int tx = threadIdx.x, ty = threadIdx.y, tz = threadIdx.z;
    int tid = (tz * 8 + ty) * 8 + tx;

    __shared__ float s_in[8][10][10][10];   // 8 cin x 10^3 halo tile (32 KB)

    float acc[8];
#pragma unroll
    for (int i = 0; i < 5; i++) acc[i] = c_cls_b[i];
#pragma unroll
    for (int i = 0; i < 3; i++) acc[5 + i] = c_off_b[i];

    for (int cg = 0; cg < 8; cg++) {
        __syncthreads();
        for (int idx = tid; idx < 8000; idx += 512) {
            int ci = idx / 1000;
            int r  = idx - ci * 1000;
            int z = r / 100, y = (r / 10) % 10, x = r % 10;
            int gz = z0 + z - 1, gy = y0 + y - 1, gx = x0 + x - 1;
            float v = 0.f;
            if ((unsigned)gz < 64u && (unsigned)gy < 64u && (unsigned)gx < 64u)
                v = feat[(((size_t)(b * 64 + cg * 8 + ci) * 64 + gz) * 64 + gy) * 64 + gx];
            s_in[ci][z][y][x] = v;
        }
        __syncthreads();

#pragma unroll 1
        for (int ci = 0; ci < 8; ci++) {
            int cw = (cg * 8 + ci) * 27;
#pragma unroll
            for (int t = 0; t < 27; t++) {
                int dz = t / 9, dy = (t / 3) % 3, dx = t % 3;
                float v = s_in[ci][tz + dz][ty + dy][tx + dx];
#pragma unroll
                for (int oc = 0; oc < 5; oc++)
                    acc[oc] += v * c_cls_w[oc * 1728 + cw + t];
#pragma unroll
                for (int oc = 0; oc < 3; oc++)
                    acc[5 + oc] += v * c_off_w[oc * 1728 + cw + t];
            }
        }
    }

    int m = (z0 + tz) * 4096 + (y0 + ty) * 64 + (x0 + tx);
#pragma unroll
    for (int oc = 0; oc < 5; oc++)
        out[(size_t)(b * 5 + oc) * NSPAT + m] = acc[oc];
#pragma unroll
    for (int oc = 0; oc < 3; oc++)
        out[OFFSETS_OFF + (size_t)(b * 3 + oc) * NSPAT + m] = acc[5 + oc];
}

// ---------------------------------------------------------------------------
// Per-GT argmax of IOU over all anchors (first-max tie-break like jnp.argmax)
// ---------------------------------------------------------------------------
__global__ __launch_bounds__(256) void best_anchor_kernel(const float* __restrict__ out,
                                                          const float* __restrict__ labels) {
    int b = blockIdx.x >> 6;
    int n = blockIdx.x & 63;
    int tid = threadIdx.x;

    float tzc = labels[(b * 5 + 0) * 64 + n];
    float tyc = labels[(b * 5 + 1) * 64 + n];
    float txc = labels[(b * 5 + 2) * 64 + n];
    float sg  = labels[(b * 5 + 4) * 64 + n];
    float inv = 1.f / (2.f * sg * sg);

    const float* off = out + OFFSETS_OFF + (size_t)b * 3 * NSPAT;

    float best = -2.f;
    int   bidx = 0x7FFFFFFF;
    for (int m = tid; m < NSPAT; m += 256) {
        int z = m >> 12, y = (m >> 6) & 63, x = m & 63;
        float pz = (z + 0.5f) * 32.f + off[m];
        float py = (y + 0.5f) * 32.f + off[NSPAT + m];
        float px = (x + 0.5f) * 32.f + off[2 * NSPAT + m];
        float dz = pz - tzc, dy = py - tyc, dx = px - txc;
        float d = dz * dz + dy * dy + dx * dx;
        float iou = expf(-d * inv);
        if (iou > best) { best = iou; bidx = m; }  // m ascending => first max
    }

    __shared__ float sv[256];
    __shared__ int   si[256];
    sv[tid] = best; si[tid] = bidx;
    __syncthreads();
    for (int s = 128; s > 0; s >>= 1) {
        if (tid < s) {
            if (sv[tid + s] > sv[tid] ||
                (sv[tid + s] == sv[tid] && si[tid + s] < si[tid])) {
                sv[tid] = sv[tid + s]; si[tid] = si[tid + s];
            }
        }
        __syncthreads();
    }
    if (tid == 0) g_best[b * 64 + n] = si[0];
}

__global__ void init_kernel() { g_loss[0] = 0.0; }

__device__ __forceinline__ float logsig(float x) {
    return fminf(x, 0.f) - log1pf(expf(-fabsf(x)));
}

// ---------------------------------------------------------------------------
// Fused matched/focal/reg loss; double block-reduce + double atomics
// ---------------------------------------------------------------------------
__global__ __launch_bounds__(256) void loss_kernel(const float* __restrict__ out,
                                                   const float* __restrict__ labels) {
    int b   = blockIdx.y;
    int tid = threadIdx.x;
    int m   = blockIdx.x * 256 + tid;

    __shared__ int   s_best[64];
    __shared__ int   s_cls[64];
    __shared__ float s_gt0[4];
    if (tid < 64) {
        s_best[tid] = g_best[b * 64 + tid];
        float c = labels[(b * 5 + 3) * 64 + tid];
        s_cls[tid] = (c < -0.5f) ? -1 : (int)c;
    }
    if (tid == 0) {
        float sg = labels[(b * 5 + 4) * 64 + 0];
        s_gt0[0] = labels[(b * 5 + 0) * 64 + 0];
        s_gt0[1] = labels[(b * 5 + 1) * 64 + 0];
        s_gt0[2] = labels[(b * 5 + 2) * 64 + 0];
        s_gt0[3] = 1.f / (2.f * sg * sg);
    }
    __syncthreads();

    int matched = -1;
    for (int n = 0; n < 64; n++)
        if (s_cls[n] >= 0 && s_best[n] == m) matched = n;   // ascending => max n
    int assigned = (matched >= 0) ? s_cls[matched] : -1;

    const float* lg = out + (size_t)b * 5 * NSPAT;
    float csum = 0.f;
#pragma unroll
    for (int c = 0; c < 5; c++) {
        float x = lg[(size_t)c * NSPAT + m];
        float p = 1.f / (1.f + expf(-x));
        if (c == assigned) { float q = 1.f - p; csum -= q * q * logsig(x); }
        else               {                    csum -= p * p * logsig(-x); }
    }

    float r = 0.f;
    if (matched < 0) {
        const float* off = out + OFFSETS_OFF + (size_t)b * 3 * NSPAT;
        int z = m >> 12, y = (m >> 6) & 63, x = m & 63;
        float pz = (z + 0.5f) * 32.f + off[m];
        float py = (y + 0.5f) * 32.f + off[NSPAT + m];
        float px = (x + 0.5f) * 32.f + off[2 * NSPAT + m];
        float dz = pz - s_gt0[0], dy = py - s_gt0[1], dx = px - s_gt0[2];
        float d = dz * dz + dy * dy + dx * dx;
        r = 1.f - expf(-d * s_gt0[3]);
    }

    __shared__ double sd[256];
    sd[tid] = (double)csum + (double)r;
    __syncthreads();
    for (int s = 128; s > 0; s >>= 1) {
        if (tid < s) sd[tid] += sd[tid + s];
        __syncthreads();
    }
    if (tid == 0) atomicAdd(&g_loss[0], sd[0]);
}

__global__ void finalize_kernel(const void* __restrict__ nitems, float* __restrict__ out) {
    long long iv = ((const int*)nitems)[0];
    float     fv = ((const float*)nitems)[0];
    double n = (iv >= 1 && iv <= 1048576) ? (double)iv : (double)fv;
    out[LOSS_OFF] = (float)(g_loss[0] / n);
}

// ---------------------------------------------------------------------------
extern "C" void kernel_launch(void* const* d_in, const int* in_sizes, int n_in,
                              void* d_out, int out_size) {
    const float* feat   = (const float*)d_in[0];
    const float* labels = (const float*)d_in[1];

    cudaMemcpyToSymbolAsync(c_cls_w, d_in[2], 5 * 64 * 27 * sizeof(float), 0,
                            cudaMemcpyDeviceToDevice, 0);
    cudaMemcpyToSymbolAsync(c_cls_b, d_in[3], 5 * sizeof(float), 0,
                            cudaMemcpyDeviceToDevice, 0);
    cudaMemcpyToSymbolAsync(c_off_w, d_in[4], 3 * 64 * 27 * sizeof(float), 0,
                            cudaMemcpyDeviceToDevice, 0);
    cudaMemcpyToSymbolAsync(c_off_b, d_in[5], 3 * sizeof(float), 0,
                            cudaMemcpyDeviceToDevice, 0);

    float* out = (float*)d_out;

    conv_kernel<<<dim3(8, 8, 16), dim3(8, 8, 8)>>>(feat, out);
    init_kernel<<<1, 1>>>();
    best_anchor_kernel<<<128, 256>>>(out, labels);
    loss_kernel<<<dim3(1024, 2), 256>>>(out, labels);
    finalize_kernel<<<1, 1>>>(d_in[6], out);
}

// round 2
// speedup vs baseline: 1.7922x; 1.7922x over previous
#include <cuda_runtime.h>
#include <cuda_bf16.h>
#include <math.h>

#define NSPAT (64*64*64)
#define OFFSETS_OFF (2*5*NSPAT)
#define LOSS_OFF (16*NSPAT)

// 134MB scratch: featT[b][z][y][x][0:64]=bf16 hi, [64:128]=bf16 lo
__device__ __align__(16) __nv_bfloat16 g_featT[(size_t)2*64*64*64*128];
__device__ unsigned long long g_key[128];   // per (b,gt): (d_bits<<32)|anchor
__device__ double g_loss[1];

// ---------------------------------------------------------------------------
// Pass 1: NCDHW fp32 -> NHWC bf16 hi/lo
// ---------------------------------------------------------------------------
__global__ __launch_bounds__(256) void transpose_kernel(const float* __restrict__ feat) {
    __shared__ float s[64][65];
    int y = blockIdx.x, z = blockIdx.y, b = blockIdx.z;
    int tid = threadIdx.x;
    const float* base = feat + (size_t)b * 64 * NSPAT + z * 4096 + y * 64;
    for (int i = tid; i < 4096; i += 256) {
        int c = i >> 6, x = i & 63;
        s[c][x] = base[(size_t)c * NSPAT + x];
    }
    __syncthreads();
    __nv_bfloat16* dst = g_featT + ((((size_t)b * 64 + z) * 64 + y) * 64) * 128;
    for (int i = tid; i < 4096; i += 256) {
        int v = i >> 6, c = i & 63;
        float val = s[c][v];
        __nv_bfloat16 hi = __float2bfloat16(val);
        __nv_bfloat16 lo = __float2bfloat16(val - __bfloat162float(hi));
        dst[v * 128 + c]      = hi;
        dst[v * 128 + 64 + c] = lo;
    }
}

// ---------------------------------------------------------------------------
// Pass 2: implicit-GEMM conv via mma.sync m16n8k16 bf16 (3-term hi/lo split)
// ---------------------------------------------------------------------------
__device__ __forceinline__ void writeOut(float* out, int b, int n, int m, float v) {
    if (n < 5) out[(size_t)(b * 5 + n) * NSPAT + m] = v;
    else       out[OFFSETS_OFF + (size_t)(b * 3 + (n - 5)) * NSPAT + m] = v;
}

#define MMA_B16(ac, a0,a1,a2,a3, b64) \
    asm volatile("mma.sync.aligned.m16n8k16.row.col.f32.bf16.bf16.f32 " \
        "{%0,%1,%2,%3}, {%4,%5,%6,%7}, {%8,%9}, {%0,%1,%2,%3};" \
        : "+f"(ac[0]), "+f"(ac[1]), "+f"(ac[2]), "+f"(ac[3]) \
        : "r"(a0), "r"(a1), "r"(a2), "r"(a3), \
          "r"((unsigned)(b64)), "r"((unsigned)((b64) >> 32)))

extern __shared__ unsigned char s_dyn[];

__global__ __launch_bounds__(256) void conv_mma_kernel(
        const float* __restrict__ cls_w, const float* __restrict__ cls_b,
        const float* __restrict__ off_w, const float* __restrict__ off_b,
        float* __restrict__ out) {
    int z = blockIdx.x, y0 = blockIdx.y * 4, b = blockIdx.z;
    int tid = threadIdx.x, lane = tid & 31, warp = tid >> 5;

    uint4* s_row = (uint4*)s_dyn;                                        // 66 voxels * 16 chunks
    unsigned long long* s_tab = (unsigned long long*)(s_dyn + 16896);    // 27*2*4*32 u64
    unsigned s_row_addr = (unsigned)__cvta_generic_to_shared(s_dyn);

    // Build B fragments: [tap][split(hi,lo)][kc][lane] -> 2 packed bf16x2
    for (int i = tid; i < 6912; i += 256) {
        int l = i & 31, kc = (i >> 5) & 3, split = (i >> 7) & 1, tap = i >> 8;
        int n = l >> 2, k0 = (l & 3) * 2;
        int kk = kc * 16 + k0;
        const float* w = (n < 5) ? (cls_w + n * 1728) : (off_w + (n - 5) * 1728);
        float w0 = w[kk * 27 + tap],       w1 = w[(kk + 1) * 27 + tap];
        float w8 = w[(kk + 8) * 27 + tap], w9 = w[(kk + 9) * 27 + tap];
        if (split) {
            w0 -= __bfloat162float(__float2bfloat16(w0));
            w1 -= __bfloat162float(__float2bfloat16(w1));
            w8 -= __bfloat162float(__float2bfloat16(w8));
            w9 -= __bfloat162float(__float2bfloat16(w9));
        }
        unsigned r0 = (unsigned)__bfloat16_as_ushort(__float2bfloat16(w0))
                    | ((unsigned)__bfloat16_as_ushort(__float2bfloat16(w1)) << 16);
        unsigned r1 = (unsigned)__bfloat16_as_ushort(__float2bfloat16(w8))
                    | ((unsigned)__bfloat16_as_ushort(__float2bfloat16(w9)) << 16);
        s_tab[i] = (unsigned long long)r0 | ((unsigned long long)r1 << 32);
    }
    // zero x-halo pad voxels 0 and 65
    if (tid < 32) {
        int v = (tid < 16) ? 0 : 65;
        s_row[v * 16 + (tid & 15)] = make_uint4(0, 0, 0, 0);
    }

    float acc[2][4];
    int n0 = (lane & 3) * 2;
    float bi0 = (n0 < 5)     ? cls_b[n0]     : off_b[n0 - 5];
    float bi1 = (n0 + 1 < 5) ? cls_b[n0 + 1] : off_b[n0 - 4];
#pragma unroll
    for (int p = 0; p < 2; p++) { acc[p][0]=bi0; acc[p][1]=bi1; acc[p][2]=bi0; acc[p][3]=bi1; }

    for (int zz = 0; zz < 3; zz++) {
        int zp = z + zz - 1;
        if ((unsigned)zp >= 64u) continue;
        for (int yy = 0; yy < 6; yy++) {
            int yp = y0 + yy - 1;
            if ((unsigned)yp >= 64u) continue;
            __syncthreads();
            const uint4* src = (const uint4*)(g_featT +
                ((((size_t)b * 64 + zp) * 64 + yp) * 64) * 128);
            for (int i = tid; i < 1024; i += 256) {
                int v = (i >> 4) + 1, ch = i & 15;
                s_row[v * 16 + (ch ^ (v & 7))] = src[i];   // XOR-swizzle for ldmatrix
            }
            __syncthreads();
#pragma unroll
            for (int p = 0; p < 2; p++) {
                int tau = warp + p * 8;
                int row = tau >> 2, q = tau & 3;
                int dy = yp - (y0 + row) + 1;
                if ((unsigned)dy > 2u) continue;
                int tapbase = (zz * 3 + dy) * 3;
#pragma unroll
                for (int dx = 0; dx < 3; dx++) {
                    int tap = tapbase + dx;
                    int vs = 16 * q + dx + (lane & 15);
                    const unsigned long long* tb = s_tab + tap * 256 + lane;
#pragma unroll
                    for (int kc = 0; kc < 4; kc++) {
                        int chunk = 2 * kc + (lane >> 4);
                        unsigned aAddr = s_row_addr + (unsigned)((vs * 16 + (chunk ^ (vs & 7))) * 16);
                        unsigned ah0, ah1, ah2, ah3, al0, al1, al2, al3;
                        asm volatile("ldmatrix.sync.aligned.m8n8.x4.shared.b16 {%0,%1,%2,%3}, [%4];"
                            : "=r"(ah0), "=r"(ah1), "=r"(ah2), "=r"(ah3) : "r"(aAddr));
                        asm volatile("ldmatrix.sync.aligned.m8n8.x4.shared.b16 {%0,%1,%2,%3}, [%4];"
                            : "=r"(al0), "=r"(al1), "=r"(al2), "=r"(al3) : "r"(aAddr + 128));
                        unsigned long long bh = tb[kc * 32];
                        unsigned long long bl = tb[128 + kc * 32];
                        MMA_B16(acc[p], ah0, ah1, ah2, ah3, bh);   // hi * w_hi
                        MMA_B16(acc[p], ah0, ah1, ah2, ah3, bl);   // hi * w_lo
                        MMA_B16(acc[p], al0, al1, al2, al3, bh);   // lo * w_hi
                    }
                }
            }
        }
    }
#pragma unroll
    for (int p = 0; p < 2; p++) {
        int tau = warp + p * 8, row = tau >> 2, q = tau & 3;
        int m0 = lane >> 2;
        int mg = z * 4096 + (y0 + row) * 64 + 16 * q + m0;
        writeOut(out, b, n0,     mg,     acc[p][0]);
        writeOut(out, b, n0 + 1, mg,     acc[p][1]);
        writeOut(out, b, n0,     mg + 8, acc[p][2]);
        writeOut(out, b, n0 + 1, mg + 8, acc[p][3]);
    }
}

// ---------------------------------------------------------------------------
// Best anchor per GT: argmax(exp(-d*inv)) == argmin(d). u64 atomicMin key.
// ---------------------------------------------------------------------------
__global__ void init_kernel() {
    int t = threadIdx.x;
    if (t < 128) g_key[t] = 0xFFFFFFFFFFFFFFFFull;
    if (t == 128) g_loss[0] = 0.0;
}

__global__ __launch_bounds__(256) void best_anchor_kernel(const float* __restrict__ out,
                                                          const float* __restrict__ labels) {
    int b = blockIdx.y, tid = threadIdx.x, lane = tid & 31, warp = tid >> 5;
    int base = blockIdx.x * 2048;
    const float* off = out + OFFSETS_OFF + (size_t)b * 3 * NSPAT;

    float pz[8], py[8], px[8];
#pragma unroll
    for (int i = 0; i < 8; i++) {
        int m = base + i * 256 + tid;
        int zc = m >> 12, yc = (m >> 6) & 63, xc = m & 63;
        pz[i] = (zc + 0.5f) * 32.f + off[m];
        py[i] = (yc + 0.5f) * 32.f + off[NSPAT + m];
        px[i] = (xc + 0.5f) * 32.f + off[2 * NSPAT + m];
    }
    __shared__ float sc[3][64];
    __shared__ unsigned long long s_red[64][8];
    if (tid < 192) { int d = tid >> 6, n = tid & 63; sc[d][n] = labels[(b * 5 + d) * 64 + n]; }
    __syncthreads();

    for (int n = 0; n < 64; n++) {
        float tz = sc[0][n], ty = sc[1][n], tx = sc[2][n];
        unsigned long long best = 0xFFFFFFFFFFFFFFFFull;
#pragma unroll
        for (int i = 0; i < 8; i++) {
            float dz = pz[i] - tz, dy = py[i] - ty, dx = px[i] - tx;
            float d = dz * dz + dy * dy + dx * dx;
            unsigned long long key = ((unsigned long long)__float_as_uint(d) << 32)
                                   | (unsigned)(base + i * 256 + tid);
            best = min(best, key);
        }
#pragma unroll
        for (int s = 16; s; s >>= 1)
            best = min(best, __shfl_down_sync(0xFFFFFFFFu, best, s));
        if (lane == 0) s_red[n][warp] = best;
    }
    __syncthreads();
    if (tid < 64) {
        unsigned long long best = s_red[tid][0];
#pragma unroll
        for (int w = 1; w < 8; w++) best = min(best, s_red[tid][w]);
        atomicMin(&g_key[b * 64 + tid], best);
    }
}

// ---------------------------------------------------------------------------
// Focal + reg loss; smem scatter map instead of per-thread 64-scan
// ---------------------------------------------------------------------------
__device__ __forceinline__ float logsig(float x) {
    return fminf(x, 0.f) - log1pf(expf(-fabsf(x)));
}

__global__ __launch_bounds__(256) void loss_kernel(const float* __restrict__ out,
                                                   const float* __restrict__ labels) {
    int b = blockIdx.y, tid = threadIdx.x;
    int m0 = blockIdx.x * 256, m = m0 + tid;

    __shared__ int   s_match[256];
    __shared__ float s_gt0[4];
    s_match[tid] = -1;
    __syncthreads();
    if (tid < 64) {
        float c = labels[(b * 5 + 3) * 64 + tid];
        if (c >= -0.5f) {
            int bm = (int)(unsigned)(g_key[b * 64 + tid] & 0xFFFFFFFFull);
            if (bm >= m0 && bm < m0 + 256) atomicMax(&s_match[bm - m0], tid);
        }
    }
    if (tid == 128) {
        float sg = labels[(b * 5 + 4) * 64];
        s_gt0[0] = labels[(b * 5 + 0) * 64];
        s_gt0[1] = labels[(b * 5 + 1) * 64];
        s_gt0[2] = labels[(b * 5 + 2) * 64];
        s_gt0[3] = 1.f / (2.f * sg * sg);
    }
    __syncthreads();

    int matched = s_match[tid];
    int assigned = (matched >= 0) ? (int)labels[(b * 5 + 3) * 64 + matched] : -1;

    const float* lg = out + (size_t)b * 5 * NSPAT;
    float csum = 0.f;
#pragma unroll
    for (int c = 0; c < 5; c++) {
        float x = lg[(size_t)c * NSPAT + m];
        float p = 1.f / (1.f + expf(-x));
        if (c == assigned) { float q = 1.f - p; csum -= q * q * logsig(x); }
        else               {                    csum -= p * p * logsig(-x); }
    }

    float r = 0.f;
    if (matched < 0) {
        const float* off = out + OFFSETS_OFF + (size_t)b * 3 * NSPAT;
        int z = m >> 12, y = (m >> 6) & 63, x = m & 63;
        float pz = (z + 0.5f) * 32.f + off[m];
        float py = (y + 0.5f) * 32.f + off[NSPAT + m];
        float px = (x + 0.5f) * 32.f + off[2 * NSPAT + m];
        float dz = pz - s_gt0[0], dy = py - s_gt0[1], dx = px - s_gt0[2];
        float d = dz * dz + dy * dy + dx * dx;
        r = 1.f - expf(-d * s_gt0[3]);
    }

    __shared__ double sd[256];
    sd[tid] = (double)csum + (double)r;
    __syncthreads();
    for (int s = 128; s > 0; s >>= 1) {
        if (tid < s) sd[tid] += sd[tid + s];
        __syncthreads();
    }
    if (tid == 0) atomicAdd(&g_loss[0], sd[0]);
}

__global__ void finalize_kernel(const void* __restrict__ nitems, float* __restrict__ out) {
    long long iv = ((const int*)nitems)[0];
    float     fv = ((const float*)nitems)[0];
    double n = (iv >= 1 && iv <= 1048576) ? (double)iv : (double)fv;
    out[LOSS_OFF] = (float)(g_loss[0] / n);
}

// ---------------------------------------------------------------------------
extern "C" void kernel_launch(void* const* d_in, const int* in_sizes, int n_in,
                              void* d_out, int out_size) {
    const float* feat   = (const float*)d_in[0];
    const float* labels = (const float*)d_in[1];
    const float* cls_w  = (const float*)d_in[2];
    const float* cls_b  = (const float*)d_in[3];
    const float* off_w  = (const float*)d_in[4];
    const float* off_b  = (const float*)d_in[5];
    float* out = (float*)d_out;

    cudaFuncSetAttribute(conv_mma_kernel, cudaFuncAttributeMaxDynamicSharedMemorySize, 72192);

    transpose_kernel<<<dim3(64, 64, 2), 256>>>(feat);
    init_kernel<<<1, 256>>>();
    conv_mma_kernel<<<dim3(64, 16, 2), 256, 72192>>>(cls_w, cls_b, off_w, off_b, out);
    best_anchor_kernel<<<dim3(128, 2), 256>>>(out, labels);
    loss_kernel<<<dim3(1024, 2), 256>>>(out, labels);
    finalize_kernel<<<1, 1>>>(d_in[6], out);
}

// round 3
// speedup vs baseline: 2.7285x; 1.5224x over previous
#include <cuda_runtime.h>
#include <cuda_bf16.h>
#include <math.h>

#define NSPAT (64*64*64)
#define OFFSETS_OFF (2*5*NSPAT)
#define LOSS_OFF (16*NSPAT)

// 134MB scratch: featT[b][z][y][x][0:64]=bf16 hi, [64:128]=bf16 lo
__device__ __align__(16) __nv_bfloat16 g_featT[(size_t)2*64*64*64*128];
__device__ __align__(16) unsigned long long g_btab[6912]; // [tap][split][kc][lane]
__device__ unsigned long long g_key[128];
__device__ double g_loss[1];

// ---------------------------------------------------------------------------
// Pass 1: NCDHW fp32 -> NHWC bf16 hi/lo
// ---------------------------------------------------------------------------
__global__ __launch_bounds__(256) void transpose_kernel(const float* __restrict__ feat) {
    __shared__ float s[64][65];
    int y = blockIdx.x, z = blockIdx.y, b = blockIdx.z;
    int tid = threadIdx.x;
    const float* base = feat + (size_t)b * 64 * NSPAT + z * 4096 + y * 64;
    for (int i = tid; i < 4096; i += 256) {
        int c = i >> 6, x = i & 63;
        s[c][x] = base[(size_t)c * NSPAT + x];
    }
    __syncthreads();
    __nv_bfloat16* dst = g_featT + ((((size_t)b * 64 + z) * 64 + y) * 64) * 128;
    for (int i = tid; i < 4096; i += 256) {
        int v = i >> 6, c = i & 63;
        float val = s[c][v];
        __nv_bfloat16 hi = __float2bfloat16(val);
        __nv_bfloat16 lo = __float2bfloat16(val - __bfloat162float(hi));
        dst[v * 128 + c]      = hi;
        dst[v * 128 + 64 + c] = lo;
    }
}

// ---------------------------------------------------------------------------
// Precompute B fragments once: [tap(27)][split(2)][kc(4)][lane(32)] -> u64
// ---------------------------------------------------------------------------
__global__ void build_tab_kernel(const float* __restrict__ cls_w,
                                 const float* __restrict__ off_w) {
    int i = blockIdx.x * 256 + threadIdx.x;     // 0..6911
    int l = i & 31, kc = (i >> 5) & 3, split = (i >> 7) & 1, tap = i >> 8;
    int n = l >> 2, k0 = (l & 3) * 2;
    int kk = kc * 16 + k0;
    const float* w = (n < 5) ? (cls_w + n * 1728) : (off_w + (n - 5) * 1728);
    float w0 = w[kk * 27 + tap],       w1 = w[(kk + 1) * 27 + tap];
    float w8 = w[(kk + 8) * 27 + tap], w9 = w[(kk + 9) * 27 + tap];
    if (split) {
        w0 -= __bfloat162float(__float2bfloat16(w0));
        w1 -= __bfloat162float(__float2bfloat16(w1));
        w8 -= __bfloat162float(__float2bfloat16(w8));
        w9 -= __bfloat162float(__float2bfloat16(w9));
    }
    unsigned r0 = (unsigned)__bfloat16_as_ushort(__float2bfloat16(w0))
                | ((unsigned)__bfloat16_as_ushort(__float2bfloat16(w1)) << 16);
    unsigned r1 = (unsigned)__bfloat16_as_ushort(__float2bfloat16(w8))
                | ((unsigned)__bfloat16_as_ushort(__float2bfloat16(w9)) << 16);
    g_btab[i] = (unsigned long long)r0 | ((unsigned long long)r1 << 32);
}

// ---------------------------------------------------------------------------
// Pass 2: implicit-GEMM conv, 4z x 4y macro tile, cp.async double buffer
// ---------------------------------------------------------------------------
__device__ __forceinline__ void writeOut(float* out, int b, int n, int m, float v) {
    if (n < 5) out[(size_t)(b * 5 + n) * NSPAT + m] = v;
    else       out[OFFSETS_OFF + (size_t)(b * 3 + (n - 5)) * NSPAT + m] = v;
}

#define MMA_B16(ac, a0,a1,a2,a3, b64) \
    asm volatile("mma.sync.aligned.m16n8k16.row.col.f32.bf16.bf16.f32 " \
        "{%0,%1,%2,%3}, {%4,%5,%6,%7}, {%8,%9}, {%0,%1,%2,%3};" \
        : "+f"(ac[0]), "+f"(ac[1]), "+f"(ac[2]), "+f"(ac[3]) \
        : "r"(a0), "r"(a1), "r"(a2), "r"(a3), \
          "r"((unsigned)(b64)), "r"((unsigned)((b64) >> 32)))

// smem: buf0 @0 (16896B), buf1 @16896, table @33792 (55296B) => 89088 total
#define SM_BUF 16896
#define SM_TAB 33792
#define SM_TOTAL 89088

extern __shared__ unsigned char s_dyn[];

__global__ __launch_bounds__(256) void conv_mma_kernel(
        const float* __restrict__ cls_b, const float* __restrict__ off_b,
        float* __restrict__ out) {
    int z0 = blockIdx.x * 4, y0 = blockIdx.y * 4, b = blockIdx.z;
    int tid = threadIdx.x, lane = tid & 31, warp = tid >> 5;
    int q = warp & 3, riL = warp >> 2;

    unsigned sbase = (unsigned)__cvta_generic_to_shared(s_dyn);
    const unsigned long long* s_tab = (const unsigned long long*)(s_dyn + SM_TAB);

    // linear table copy (L2-resident after first wave)
    {
        uint4* dst = (uint4*)(s_dyn + SM_TAB);
        const uint4* src = (const uint4*)g_btab;
        for (int i = tid; i < 3456; i += 256) dst[i] = src[i];
    }
    // zero x-halo voxels (v=0,65) in both buffers
    if (tid < 64) {
        int bb = tid >> 5, idx = tid & 31;
        int v = (idx < 16) ? 0 : 65, ch = idx & 15;
        ((uint4*)(s_dyn + bb * SM_BUF))[v * 16 + ch] = make_uint4(0, 0, 0, 0);
    }

    // valid (zz,yy) rectangle
    int zzlo = (z0 == 0) ? 1 : 0, zzhi = (z0 == 60) ? 4 : 5;
    int yylo = (y0 == 0) ? 1 : 0, yyhi = (y0 == 60) ? 4 : 5;
    int ny = yyhi - yylo + 1;
    int nrow = (zzhi - zzlo + 1) * ny;

    float acc[8][4];
    int n0 = (lane & 3) * 2;
    float bi0 = (n0 < 5)     ? cls_b[n0]     : off_b[n0 - 5];
    float bi1 = (n0 + 1 < 5) ? cls_b[n0 + 1] : off_b[n0 - 4];
#pragma unroll
    for (int s = 0; s < 8; s++) { acc[s][0]=bi0; acc[s][1]=bi1; acc[s][2]=bi0; acc[s][3]=bi1; }

#define ISSUE_LOAD(I_, BUF_) do { \
    int zz_ = zzlo + (I_) / ny, yy_ = yylo + (I_) % ny; \
    const uint4* src_ = (const uint4*)(g_featT + \
        ((((size_t)b * 64 + (z0 + zz_ - 1)) * 64 + (y0 + yy_ - 1)) * 64) * 128); \
    unsigned dbase_ = sbase + (BUF_) * SM_BUF; \
    _Pragma("unroll") \
    for (int k_ = 0; k_ < 4; k_++) { \
        int i_ = tid + k_ * 256; int v_ = (i_ >> 4) + 1, ch_ = i_ & 15; \
        unsigned d_ = dbase_ + (unsigned)((v_ * 16 + (ch_ ^ (v_ & 7))) * 16); \
        asm volatile("cp.async.cg.shared.global [%0], [%1], 16;" :: "r"(d_), "l"(src_ + i_)); \
    } \
    asm volatile("cp.async.commit_group;"); \
} while (0)

    ISSUE_LOAD(0, 0);

    for (int i = 0; i < nrow; i++) {
        if (i + 1 < nrow) {
            ISSUE_LOAD(i + 1, (i + 1) & 1);
            asm volatile("cp.async.wait_group 1;");
        } else {
            asm volatile("cp.async.wait_group 0;");
        }
        __syncthreads();

        int zz = zzlo + i / ny, yy = yylo + i % ny;
        unsigned abase = sbase + (i & 1) * SM_BUF;

#pragma unroll
        for (int dx = 0; dx < 3; dx++) {
#pragma unroll
            for (int kc = 0; kc < 4; kc++) {
                int vs = 16 * q + dx + (lane & 15);
                int chunk = 2 * kc + (lane >> 4);
                unsigned aAddr = abase + (unsigned)((vs * 16 + (chunk ^ (vs & 7))) * 16);
                unsigned ah0, ah1, ah2, ah3, al0, al1, al2, al3;
                asm volatile("ldmatrix.sync.aligned.m8n8.x4.shared.b16 {%0,%1,%2,%3}, [%4];"
                    : "=r"(ah0), "=r"(ah1), "=r"(ah2), "=r"(ah3) : "r"(aAddr));
                asm volatile("ldmatrix.sync.aligned.m8n8.x4.shared.b16 {%0,%1,%2,%3}, [%4];"
                    : "=r"(al0), "=r"(al1), "=r"(al2), "=r"(al3) : "r"(aAddr + 128));
#pragma unroll
                for (int zi = 0; zi < 4; zi++) {
                    int dzt = zz - zi;
                    if ((unsigned)dzt > 2u) continue;          // warp-uniform
#pragma unroll
                    for (int rih = 0; rih < 2; rih++) {
                        int ri = rih * 2 + riL;
                        int dyt = yy - ri;
                        if ((unsigned)dyt > 2u) continue;      // warp-uniform
                        int tap = (dzt * 3 + dyt) * 3 + dx;
                        const unsigned long long* tb = s_tab + tap * 256 + lane;
                        unsigned long long bh = tb[kc * 32];
                        unsigned long long bl = tb[kc * 32 + 128];
                        MMA_B16(acc[zi * 2 + rih], ah0, ah1, ah2, ah3, bh);
                        MMA_B16(acc[zi * 2 + rih], ah0, ah1, ah2, ah3, bl);
                        MMA_B16(acc[zi * 2 + rih], al0, al1, al2, al3, bh);
                    }
                }
            }
        }
        __syncthreads();
    }

#pragma unroll
    for (int s = 0; s < 8; s++) {
        int zi = s >> 1, ri = (s & 1) * 2 + riL;
        int mg = (z0 + zi) * 4096 + (y0 + ri) * 64 + 16 * q + (lane >> 2);
        writeOut(out, b, n0,     mg,     acc[s][0]);
        writeOut(out, b, n0 + 1, mg,     acc[s][1]);
        writeOut(out, b, n0,     mg + 8, acc[s][2]);
        writeOut(out, b, n0 + 1, mg + 8, acc[s][3]);
    }
}

// ---------------------------------------------------------------------------
// Best anchor per GT: argmin(d) with u64 (d_bits<<32|idx) atomicMin
// ---------------------------------------------------------------------------
__global__ void init_kernel() {
    int t = threadIdx.x;
    if (t < 128) g_key[t] = 0xFFFFFFFFFFFFFFFFull;
    if (t == 128) g_loss[0] = 0.0;
}

__global__ __launch_bounds__(256) void best_anchor_kernel(const float* __restrict__ out,
                                                          const float* __restrict__ labels) {
    int b = blockIdx.y, tid = threadIdx.x, lane = tid & 31, warp = tid >> 5;
    int base = blockIdx.x * 1024;
    const float* off = out + OFFSETS_OFF + (size_t)b * 3 * NSPAT;

    float pz[4], py[4], px[4];
#pragma unroll
    for (int i = 0; i < 4; i++) {
        int m = base + i * 256 + tid;
        int zc = m >> 12, yc = (m >> 6) & 63, xc = m & 63;
        pz[i] = (zc + 0.5f) * 32.f + off[m];
        py[i] = (yc + 0.5f) * 32.f + off[NSPAT + m];
        px[i] = (xc + 0.5f) * 32.f + off[2 * NSPAT + m];
    }
    __shared__ float sc[3][64];
    __shared__ unsigned long long s_red[64][8];
    if (tid < 192) { int d = tid >> 6, n = tid & 63; sc[d][n] = labels[(b * 5 + d) * 64 + n]; }
    __syncthreads();

    for (int n = 0; n < 64; n++) {
        float tz = sc[0][n], ty = sc[1][n], tx = sc[2][n];
        unsigned long long best = 0xFFFFFFFFFFFFFFFFull;
#pragma unroll
        for (int i = 0; i < 4; i++) {
            float dz = pz[i] - tz, dy = py[i] - ty, dx = px[i] - tx;
            float d = dz * dz + dy * dy + dx * dx;
            unsigned long long key = ((unsigned long long)__float_as_uint(d) << 32)
                                   | (unsigned)(base + i * 256 + tid);
            best = min(best, key);
        }
#pragma unroll
        for (int s = 16; s; s >>= 1)
            best = min(best, __shfl_down_sync(0xFFFFFFFFu, best, s));
        if (lane == 0) s_red[n][warp] = best;
    }
    __syncthreads();
    if (tid < 64) {
        unsigned long long best = s_red[tid][0];
#pragma unroll
        for (int w = 1; w < 8; w++) best = min(best, s_red[tid][w]);
        atomicMin(&g_key[b * 64 + tid], best);
    }
}

// ---------------------------------------------------------------------------
// Focal + reg loss
// ---------------------------------------------------------------------------
__device__ __forceinline__ float logsig(float x) {
    return fminf(x, 0.f) - log1pf(expf(-fabsf(x)));
}

__global__ __launch_bounds__(256) void loss_kernel(const float* __restrict__ out,
                                                   const float* __restrict__ labels) {
    int b = blockIdx.y, tid = threadIdx.x;
    int m0 = blockIdx.x * 256, m = m0 + tid;

    __shared__ int   s_match[256];
    __shared__ float s_gt0[4];
    s_match[tid] = -1;
    __syncthreads();
    if (tid < 64) {
        float c = labels[(b * 5 + 3) * 64 + tid];
        if (c >= -0.5f) {
            int bm = (int)(unsigned)(g_key[b * 64 + tid] & 0xFFFFFFFFull);
            if (bm >= m0 && bm < m0 + 256) atomicMax(&s_match[bm - m0], tid);
        }
    }
    if (tid == 128) {
        float sg = labels[(b * 5 + 4) * 64];
        s_gt0[0] = labels[(b * 5 + 0) * 64];
        s_gt0[1] = labels[(b * 5 + 1) * 64];
        s_gt0[2] = labels[(b * 5 + 2) * 64];
        s_gt0[3] = 1.f / (2.f * sg * sg);
    }
    __syncthreads();

    int matched = s_match[tid];
    int assigned = (matched >= 0) ? (int)labels[(b * 5 + 3) * 64 + matched] : -1;

    const float* lg = out + (size_t)b * 5 * NSPAT;
    float csum = 0.f;
#pragma unroll
    for (int c = 0; c < 5; c++) {
        float x = lg[(size_t)c * NSPAT + m];
        float p = 1.f / (1.f + expf(-x));
        if (c == assigned) { float qq = 1.f - p; csum -= qq * qq * logsig(x); }
        else               {                     csum -= p * p * logsig(-x); }
    }

    float r = 0.f;
    if (matched < 0) {
        const float* off = out + OFFSETS_OFF + (size_t)b * 3 * NSPAT;
        int z = m >> 12, y = (m >> 6) & 63, x = m & 63;
        float pz = (z + 0.5f) * 32.f + off[m];
        float py = (y + 0.5f) * 32.f + off[NSPAT + m];
        float px = (x + 0.5f) * 32.f + off[2 * NSPAT + m];
        float dz = pz - s_gt0[0], dy = py - s_gt0[1], dx = px - s_gt0[2];
        float d = dz * dz + dy * dy + dx * dx;
        r = 1.f - expf(-d * s_gt0[3]);
    }

    __shared__ double sd[256];
    sd[tid] = (double)csum + (double)r;
    __syncthreads();
    for (int s = 128; s > 0; s >>= 1) {
        if (tid < s) sd[tid] += sd[tid + s];
        __syncthreads();
    }
    if (tid == 0) atomicAdd(&g_loss[0], sd[0]);
}

__global__ void finalize_kernel(const void* __restrict__ nitems, float* __restrict__ out) {
    long long iv = ((const int*)nitems)[0];
    float     fv = ((const float*)nitems)[0];
    double n = (iv >= 1 && iv <= 1048576) ? (double)iv : (double)fv;
    out[LOSS_OFF] = (float)(g_loss[0] / n);
}

// ---------------------------------------------------------------------------
extern "C" void kernel_launch(void* const* d_in, const int* in_sizes, int n_in,
                              void* d_out, int out_size) {
    const float* feat   = (const float*)d_in[0];
    const float* labels = (const float*)d_in[1];
    const float* cls_w  = (const float*)d_in[2];
    const float* cls_b  = (const float*)d_in[3];
    const float* off_w  = (const float*)d_in[4];
    const float* off_b  = (const float*)d_in[5];
    float* out = (float*)d_out;

    cudaFuncSetAttribute(conv_mma_kernel, cudaFuncAttributeMaxDynamicSharedMemorySize, SM_TOTAL);

    transpose_kernel<<<dim3(64, 64, 2), 256>>>(feat);
    build_tab_kernel<<<27, 256>>>(cls_w, off_w);
    init_kernel<<<1, 256>>>();
    conv_mma_kernel<<<dim3(16, 16, 2), 256, SM_TOTAL>>>(cls_b, off_b, out);
    best_anchor_kernel<<<dim3(256, 2), 256>>>(out, labels);
    loss_kernel<<<dim3(1024, 2), 256>>>(out, labels);
    finalize_kernel<<<1, 1>>>(d_in[6], out);
}

// round 4
// speedup vs baseline: 2.7550x; 1.0097x over previous
#include <cuda_runtime.h>
#include <cuda_bf16.h>
#include <math.h>

#define NSPAT (64*64*64)
#define OFFSETS_OFF (2*5*NSPAT)
#define LOSS_OFF (16*NSPAT)

// 134MB scratch: featT[b][z][y][x][0:64]=bf16 hi, [64:128]=bf16 lo
__device__ __align__(16) __nv_bfloat16 g_featT[(size_t)2*64*64*64*128];
// B fragments: [tap(27)][kc(4)][lane(32)] -> uint4 {bh0,bh1,bl0,bl1}
__device__ __align__(16) uint4 g_btab[3456];
__device__ unsigned long long g_key[128];
__device__ double g_loss[1];

// ---------------------------------------------------------------------------
// Pass 1: NCDHW fp32 -> NHWC bf16 hi/lo
// ---------------------------------------------------------------------------
__global__ __launch_bounds__(256) void transpose_kernel(const float* __restrict__ feat) {
    __shared__ float s[64][65];
    int y = blockIdx.x, z = blockIdx.y, b = blockIdx.z;
    int tid = threadIdx.x;
    const float* base = feat + (size_t)b * 64 * NSPAT + z * 4096 + y * 64;
    for (int i = tid; i < 4096; i += 256) {
        int c = i >> 6, x = i & 63;
        s[c][x] = base[(size_t)c * NSPAT + x];
    }
    __syncthreads();
    __nv_bfloat16* dst = g_featT + ((((size_t)b * 64 + z) * 64 + y) * 64) * 128;
    for (int i = tid; i < 4096; i += 256) {
        int v = i >> 6, c = i & 63;
        float val = s[c][v];
        __nv_bfloat16 hi = __float2bfloat16(val);
        __nv_bfloat16 lo = __float2bfloat16(val - __bfloat162float(hi));
        dst[v * 128 + c]      = hi;
        dst[v * 128 + 64 + c] = lo;
    }
}

// ---------------------------------------------------------------------------
// Precompute packed B fragments once
// ---------------------------------------------------------------------------
__global__ void build_tab_kernel(const float* __restrict__ cls_w,
                                 const float* __restrict__ off_w) {
    int i = blockIdx.x * 256 + threadIdx.x;     // 0..3455
    if (i >= 3456) return;
    int l = i & 31, kc = (i >> 5) & 3, tap = i >> 7;
    int n = l >> 2, k0 = (l & 3) * 2;
    int kk = kc * 16 + k0;
    const float* w = (n < 5) ? (cls_w + n * 1728) : (off_w + (n - 5) * 1728);
    float w0 = w[kk * 27 + tap],       w1 = w[(kk + 1) * 27 + tap];
    float w8 = w[(kk + 8) * 27 + tap], w9 = w[(kk + 9) * 27 + tap];
    float l0 = w0 - __bfloat162float(__float2bfloat16(w0));
    float l1 = w1 - __bfloat162float(__float2bfloat16(w1));
    float l8 = w8 - __bfloat162float(__float2bfloat16(w8));
    float l9 = w9 - __bfloat162float(__float2bfloat16(w9));
    uint4 r;
    r.x = (unsigned)__bfloat16_as_ushort(__float2bfloat16(w0))
        | ((unsigned)__bfloat16_as_ushort(__float2bfloat16(w1)) << 16);
    r.y = (unsigned)__bfloat16_as_ushort(__float2bfloat16(w8))
        | ((unsigned)__bfloat16_as_ushort(__float2bfloat16(w9)) << 16);
    r.z = (unsigned)__bfloat16_as_ushort(__float2bfloat16(l0))
        | ((unsigned)__bfloat16_as_ushort(__float2bfloat16(l1)) << 16);
    r.w = (unsigned)__bfloat16_as_ushort(__float2bfloat16(l8))
        | ((unsigned)__bfloat16_as_ushort(__float2bfloat16(l9)) << 16);
    g_btab[i] = r;
}

// ---------------------------------------------------------------------------
// Pass 2: implicit-GEMM conv, 2z x 4y tile, 3-stage cp.async pipeline
// ---------------------------------------------------------------------------
__device__ __forceinline__ void writeOut(float* out, int b, int n, int m, float v) {
    if (n < 5) out[(size_t)(b * 5 + n) * NSPAT + m] = v;
    else       out[OFFSETS_OFF + (size_t)(b * 3 + (n - 5)) * NSPAT + m] = v;
}

#define MMA_B16(ac, a0,a1,a2,a3, b0,b1) \
    asm volatile("mma.sync.aligned.m16n8k16.row.col.f32.bf16.bf16.f32 " \
        "{%0,%1,%2,%3}, {%4,%5,%6,%7}, {%8,%9}, {%0,%1,%2,%3};" \
        : "+f"(ac[0]), "+f"(ac[1]), "+f"(ac[2]), "+f"(ac[3]) \
        : "r"(a0), "r"(a1), "r"(a2), "r"(a3), "r"(b0), "r"(b1))

#define SM_BUF 16896
#define SM_TOTAL (3*SM_BUF)

extern __shared__ unsigned char s_dyn[];

__global__ __launch_bounds__(256, 3) void conv_mma_kernel(
        const float* __restrict__ cls_b, const float* __restrict__ off_b,
        float* __restrict__ out) {
    int z0 = blockIdx.x * 2, y0 = blockIdx.y * 4, b = blockIdx.z;
    int tid = threadIdx.x, lane = tid & 31, warp = tid >> 5;
    int q = warp & 3, riL = warp >> 2;

    unsigned sbase = (unsigned)__cvta_generic_to_shared(s_dyn);

    // zero x-halo voxels (v=0,65) in all 3 buffers
    if (tid < 96) {
        int bb = tid >> 5, idx = tid & 31;
        int v = (idx < 16) ? 0 : 65, ch = idx & 15;
        ((uint4*)(s_dyn + bb * SM_BUF))[v * 16 + ch] = make_uint4(0, 0, 0, 0);
    }

    int zzlo = (z0 == 0) ? 1 : 0, zzhi = (z0 == 62) ? 2 : 3;
    int yylo = (y0 == 0) ? 1 : 0, yyhi = (y0 == 60) ? 4 : 5;
    int ny = yyhi - yylo + 1;
    int nrow = (zzhi - zzlo + 1) * ny;

    float acc[4][4];
    int n0 = (lane & 3) * 2;
    float bi0 = (n0 < 5)     ? cls_b[n0]     : off_b[n0 - 5];
    float bi1 = (n0 + 1 < 5) ? cls_b[n0 + 1] : off_b[n0 - 4];
#pragma unroll
    for (int s = 0; s < 4; s++) { acc[s][0]=bi0; acc[s][1]=bi1; acc[s][2]=bi0; acc[s][3]=bi1; }

#define ISSUE_LOAD(I_, BUF_) do { \
    int zz_ = zzlo + (I_) / ny, yy_ = yylo + (I_) % ny; \
    const uint4* src_ = (const uint4*)(g_featT + \
        ((((size_t)b * 64 + (z0 + zz_ - 1)) * 64 + (y0 + yy_ - 1)) * 64) * 128); \
    unsigned dbase_ = sbase + (BUF_) * SM_BUF; \
    _Pragma("unroll") \
    for (int k_ = 0; k_ < 4; k_++) { \
        int i_ = tid + k_ * 256; int v_ = (i_ >> 4) + 1, ch_ = i_ & 15; \
        unsigned d_ = dbase_ + (unsigned)((v_ * 16 + (ch_ ^ (v_ & 7))) * 16); \
        asm volatile("cp.async.cg.shared.global [%0], [%1], 16;" :: "r"(d_), "l"(src_ + i_)); \
    } \
    asm volatile("cp.async.commit_group;"); \
} while (0)

    ISSUE_LOAD(0, 0);
    ISSUE_LOAD(1, 1);

    for (int i = 0; i < nrow; i++) {
        if (i + 1 < nrow) asm volatile("cp.async.wait_group 1;");
        else              asm volatile("cp.async.wait_group 0;");
        __syncthreads();
        if (i + 2 < nrow) ISSUE_LOAD(i + 2, (i + 2) % 3);

        int zz = zzlo + i / ny, yy = yylo + i % ny;
        // warp-level y-activity: riL=0 handles ri{0,2} (yy<=4); riL=1 ri{1,3} (yy>=1)
        bool active = (riL == 0) ? (yy <= 4) : (yy >= 1);
        if (active) {
            unsigned abase = sbase + (unsigned)((i % 3) * SM_BUF);
#pragma unroll
            for (int dx = 0; dx < 3; dx++) {
#pragma unroll
                for (int kc = 0; kc < 4; kc++) {
                    int vs = 16 * q + dx + (lane & 15);
                    int chunk = 2 * kc + (lane >> 4);
                    unsigned aAddr = abase + (unsigned)((vs * 16 + (chunk ^ (vs & 7))) * 16);
                    unsigned ah0, ah1, ah2, ah3, al0, al1, al2, al3;
                    asm volatile("ldmatrix.sync.aligned.m8n8.x4.shared.b16 {%0,%1,%2,%3}, [%4];"
                        : "=r"(ah0), "=r"(ah1), "=r"(ah2), "=r"(ah3) : "r"(aAddr));
                    asm volatile("ldmatrix.sync.aligned.m8n8.x4.shared.b16 {%0,%1,%2,%3}, [%4];"
                        : "=r"(al0), "=r"(al1), "=r"(al2), "=r"(al3) : "r"(aAddr + 128));
#pragma unroll
                    for (int zi = 0; zi < 2; zi++) {
                        int dzt = zz - zi;
                        if ((unsigned)dzt > 2u) continue;
#pragma unroll
                        for (int rih = 0; rih < 2; rih++) {
                            int ri = rih * 2 + riL;
                            int dyt = yy - ri;
                            if ((unsigned)dyt > 2u) continue;
                            int tap = (dzt * 3 + dyt) * 3 + dx;
                            uint4 B = __ldg(&g_btab[(tap * 4 + kc) * 32 + lane]);
                            MMA_B16(acc[zi * 2 + rih], ah0, ah1, ah2, ah3, B.x, B.y);
                            MMA_B16(acc[zi * 2 + rih], ah0, ah1, ah2, ah3, B.z, B.w);
                            MMA_B16(acc[zi * 2 + rih], al0, al1, al2, al3, B.x, B.y);
                        }
                    }
                }
            }
        }
        __syncthreads();
    }

#pragma unroll
    for (int s = 0; s < 4; s++) {
        int zi = s >> 1, ri = (s & 1) * 2 + riL;
        int mg = (z0 + zi) * 4096 + (y0 + ri) * 64 + 16 * q + (lane >> 2);
        writeOut(out, b, n0,     mg,     acc[s][0]);
        writeOut(out, b, n0 + 1, mg,     acc[s][1]);
        writeOut(out, b, n0,     mg + 8, acc[s][2]);
        writeOut(out, b, n0 + 1, mg + 8, acc[s][3]);
    }
}

// ---------------------------------------------------------------------------
// Best anchor per GT: argmin(d) with u64 (d_bits<<32|idx) atomicMin
// ---------------------------------------------------------------------------
__global__ void init_kernel() {
    int t = threadIdx.x;
    if (t < 128) g_key[t] = 0xFFFFFFFFFFFFFFFFull;
    if (t == 128) g_loss[0] = 0.0;
}

__global__ __launch_bounds__(256) void best_anchor_kernel(const float* __restrict__ out,
                                                          const float* __restrict__ labels) {
    int b = blockIdx.y, tid = threadIdx.x, lane = tid & 31, warp = tid >> 5;
    int base = blockIdx.x * 1024;
    const float* off = out + OFFSETS_OFF + (size_t)b * 3 * NSPAT;

    float pz[4], py[4], px[4];
#pragma unroll
    for (int i = 0; i < 4; i++) {
        int m = base + i * 256 + tid;
        int zc = m >> 12, yc = (m >> 6) & 63, xc = m & 63;
        pz[i] = (zc + 0.5f) * 32.f + off[m];
        py[i] = (yc + 0.5f) * 32.f + off[NSPAT + m];
        px[i] = (xc + 0.5f) * 32.f + off[2 * NSPAT + m];
    }
    __shared__ float sc[3][64];
    __shared__ unsigned long long s_red[64][8];
    if (tid < 192) { int d = tid >> 6, n = tid & 63; sc[d][n] = labels[(b * 5 + d) * 64 + n]; }
    __syncthreads();

    for (int n = 0; n < 64; n++) {
        float tz = sc[0][n], ty = sc[1][n], tx = sc[2][n];
        unsigned long long best = 0xFFFFFFFFFFFFFFFFull;
#pragma unroll
        for (int i = 0; i < 4; i++) {
            float dz = pz[i] - tz, dy = py[i] - ty, dx = px[i] - tx;
            float d = dz * dz + dy * dy + dx * dx;
            unsigned long long key = ((unsigned long long)__float_as_uint(d) << 32)
                                   | (unsigned)(base + i * 256 + tid);
            best = min(best, key);
        }
#pragma unroll
        for (int s = 16; s; s >>= 1)
            best = min(best, __shfl_down_sync(0xFFFFFFFFu, best, s));
        if (lane == 0) s_red[n][warp] = best;
    }
    __syncthreads();
    if (tid < 64) {
        unsigned long long best = s_red[tid][0];
#pragma unroll
        for (int w = 1; w < 8; w++) best = min(best, s_red[tid][w]);
        atomicMin(&g_key[b * 64 + tid], best);
    }
}

// ---------------------------------------------------------------------------
// Focal + reg loss
// ---------------------------------------------------------------------------
__device__ __forceinline__ float logsig(float x) {
    return fminf(x, 0.f) - log1pf(expf(-fabsf(x)));
}

__global__ __launch_bounds__(256) void loss_kernel(const float* __restrict__ out,
                                                   const float* __restrict__ labels) {
    int b = blockIdx.y, tid = threadIdx.x;
    int m0 = blockIdx.x * 256, m = m0 + tid;

    __shared__ int   s_match[256];
    __shared__ float s_gt0[4];
    s_match[tid] = -1;
    __syncthreads();
    if (tid < 64) {
        float c = labels[(b * 5 + 3) * 64 + tid];
        if (c >= -0.5f) {
            int bm = (int)(unsigned)(g_key[b * 64 + tid] & 0xFFFFFFFFull);
            if (bm >= m0 && bm < m0 + 256) atomicMax(&s_match[bm - m0], tid);
        }
    }
    if (tid == 128) {
        float sg = labels[(b * 5 + 4) * 64];
        s_gt0[0] = labels[(b * 5 + 0) * 64];
        s_gt0[1] = labels[(b * 5 + 1) * 64];
        s_gt0[2] = labels[(b * 5 + 2) * 64];
        s_gt0[3] = 1.f / (2.f * sg * sg);
    }
    __syncthreads();

    int matched = s_match[tid];
    int assigned = (matched >= 0) ? (int)labels[(b * 5 + 3) * 64 + matched] : -1;

    const float* lg = out + (size_t)b * 5 * NSPAT;
    float csum = 0.f;
#pragma unroll
    for (int c = 0; c < 5; c++) {
        float x = lg[(size_t)c * NSPAT + m];
        float p = 1.f / (1.f + expf(-x));
        if (c == assigned) { float qq = 1.f - p; csum -= qq * qq * logsig(x); }
        else               {                     csum -= p * p * logsig(-x); }
    }

    float r = 0.f;
    if (matched < 0) {
        const float* off = out + OFFSETS_OFF + (size_t)b * 3 * NSPAT;
        int z = m >> 12, y = (m >> 6) & 63, x = m & 63;
        float pz = (z + 0.5f) * 32.f + off[m];
        float py = (y + 0.5f) * 32.f + off[NSPAT + m];
        float px = (x + 0.5f) * 32.f + off[2 * NSPAT + m];
        float dz = pz - s_gt0[0], dy = py - s_gt0[1], dx = px - s_gt0[2];
        float d = dz * dz + dy * dy + dx * dx;
        r = 1.f - expf(-d * s_gt0[3]);
    }

    __shared__ double sd[256];
    sd[tid] = (double)csum + (double)r;
    __syncthreads();
    for (int s = 128; s > 0; s >>= 1) {
        if (tid < s) sd[tid] += sd[tid + s];
        __syncthreads();
    }
    if (tid == 0) atomicAdd(&g_loss[0], sd[0]);
}

__global__ void finalize_kernel(const void* __restrict__ nitems, float* __restrict__ out) {
    long long iv = ((const int*)nitems)[0];
    float     fv = ((const float*)nitems)[0];
    double n = (iv >= 1 && iv <= 1048576) ? (double)iv : (double)fv;
    out[LOSS_OFF] = (float)(g_loss[0] / n);
}

// ---------------------------------------------------------------------------
extern "C" void kernel_launch(void* const* d_in, const int* in_sizes, int n_in,
                              void* d_out, int out_size) {
    const float* feat   = (const float*)d_in[0];
    const float* labels = (const float*)d_in[1];
    const float* cls_w  = (const float*)d_in[2];
    const float* cls_b  = (const float*)d_in[3];
    const float* off_w  = (const float*)d_in[4];
    const float* off_b  = (const float*)d_in[5];
    float* out = (float*)d_out;

    cudaFuncSetAttribute(conv_mma_kernel, cudaFuncAttributeMaxDynamicSharedMemorySize, SM_TOTAL);

    transpose_kernel<<<dim3(64, 64, 2), 256>>>(feat);
    build_tab_kernel<<<14, 256>>>(cls_w, off_w);
    init_kernel<<<1, 256>>>();
    conv_mma_kernel<<<dim3(32, 16, 2), 256, SM_TOTAL>>>(cls_b, off_b, out);
    best_anchor_kernel<<<dim3(256, 2), 256>>>(out, labels);
    loss_kernel<<<dim3(1024, 2), 256>>>(out, labels);
    finalize_kernel<<<1, 1>>>(d_in[6], out);
}